// round 16
// baseline (speedup 1.0000x reference)
#include <cuda_runtime.h>
#include <cuda_bf16.h>
#include <cstdint>

#define BB 8
#define NN 4096
#define KK 10
#define BNPTS (BB*NN)          // 32768
#define EDGE_COUNT 327680.0f   // B*N*K
#define TAU 0.2f
#define EPS 1e-5f
#define FULLMASK 0xffffffffu

// ---------------- device scratch (no allocations allowed) ----------------
__device__ int   d_nbr[BNPTS*11];
__device__ float d_buf1[BNPTS*128];     // u1(64)|v1(64)
__device__ float d_m1[BNPTS*64];        // max_k z (stage1)
__device__ float d_buf2[BNPTS*384];     // u2(128)|v2(128)|us2(64)|vs2(64)
__device__ float d_f2[BNPTS*128];
__device__ float d_buf3[BNPTS*768];     // u3(256)|v3(256)|us3(128)|vs3(128)
__device__ float d_f3[BNPTS*256];
__device__ float d_hall[BNPTS*64];
__device__ __nv_bfloat16 d_W2t_h[384*64],  d_W2t_l[384*64];    // [N][K] split
__device__ __nv_bfloat16 d_W3t_h[768*128], d_W3t_l[768*128];
__device__ __nv_bfloat16 d_Wa1t_h[64*256], d_Wa1t_l[64*256];
__device__ float d_stats[3*512];
__device__ __align__(16) float d_scale[3*256];
__device__ __align__(16) float d_shift[3*256];
__device__ unsigned d_ctr[3];
__device__ float d_wlog[BNPTS];
__device__ float d_bmax[BB];
__device__ float d_bsum[BB];
__device__ float d_pooled[BB*256];

// ---------------- packed f32x2 helpers (knn) ----------------
__device__ __forceinline__ unsigned long long ffma2(unsigned long long a,
                                                    unsigned long long b,
                                                    unsigned long long c)
{
    unsigned long long d;
    asm("fma.rn.f32x2 %0, %1, %2, %3;" : "=l"(d) : "l"(a), "l"(b), "l"(c));
    return d;
}
__device__ __forceinline__ unsigned long long pack2(float x)
{
    unsigned long long d;
    asm("mov.b64 %0, {%1, %1};" : "=l"(d) : "r"(__float_as_uint(x)));
    return d;
}
__device__ __forceinline__ unsigned long long packxy(float x, float y)
{
    unsigned long long d;
    asm("mov.b64 %0, {%1, %2};" : "=l"(d)
        : "r"(__float_as_uint(x)), "r"(__float_as_uint(y)));
    return d;
}
__device__ __forceinline__ void unpack2(unsigned long long v, float& lo, float& hi)
{
    unsigned int a, b;
    asm("mov.b64 {%0, %1}, %2;" : "=r"(a), "=r"(b) : "l"(v));
    lo = __uint_as_float(a); hi = __uint_as_float(b);
}

// ---------------- tensor helpers ----------------
__device__ __forceinline__ unsigned smem_u32(const void* p)
{
    return (unsigned)__cvta_generic_to_shared(p);
}
__device__ __forceinline__ void ldsm4(unsigned& r0, unsigned& r1,
                                      unsigned& r2, unsigned& r3, unsigned a)
{
    asm volatile("ldmatrix.sync.aligned.m8n8.x4.shared.b16 {%0,%1,%2,%3}, [%4];"
        : "=r"(r0), "=r"(r1), "=r"(r2), "=r"(r3) : "r"(a));
}
__device__ __forceinline__ void mma_bf16(float* c, const unsigned* a, const unsigned* b)
{
    asm volatile("mma.sync.aligned.m16n8k16.row.col.f32.bf16.bf16.f32 "
        "{%0,%1,%2,%3}, {%4,%5,%6,%7}, {%8,%9}, {%0,%1,%2,%3};"
        : "+f"(c[0]), "+f"(c[1]), "+f"(c[2]), "+f"(c[3])
        : "r"(a[0]), "r"(a[1]), "r"(a[2]), "r"(a[3]), "r"(b[0]), "r"(b[1]));
}
__device__ __forceinline__ void bsplit(float v, __nv_bfloat16& h, __nv_bfloat16& l)
{
    h = __float2bfloat16_rn(v);
    l = __float2bfloat16_rn(v - __bfloat162float(h));
}
__device__ __forceinline__ unsigned bfpair(__nv_bfloat16 a, __nv_bfloat16 b)
{
    return (unsigned)__bfloat16_as_ushort(a)
         | ((unsigned)__bfloat16_as_ushort(b) << 16);
}

// ---------------- KNN: threshold-filter top-11 (proven R13 config) ----------
#define KNN_WARPS 8
#define KNN_QB 8
#define KNN_BUF 64
#define KNN_SMEM (4096*16 + KNN_WARPS*KNN_QB*KNN_BUF*8)

__device__ __forceinline__ unsigned orderable_f32(float f)
{
    unsigned u = __float_as_uint(f);
    return (u & 0x80000000u) ? ~u : (u | 0x80000000u);
}

__global__ __launch_bounds__(KNN_WARPS*32) void knn_kernel(
    const float* __restrict__ x, int* __restrict__ nbr)
{
    extern __shared__ unsigned char smem_raw[];
    float4* cand = (float4*)smem_raw;
    unsigned long long* wbuf = (unsigned long long*)(cand + 4096);
    __shared__ int scnt[KNN_WARPS][KNN_QB];

    const int b    = blockIdx.y;
    const int tid  = threadIdx.x;
    const int warp = tid >> 5;
    const int lane = tid & 31;

    for (int i = tid; i < 4096; i += blockDim.x) {
        const float* xp = x + ((size_t)b*4096 + i)*5;
        float cx = xp[0], cy = xp[1], cz = xp[2];
        cand[i] = make_float4(cx, cy, cz, cx*cx + cy*cy + cz*cz);
    }
    __syncthreads();

    const int qbase = blockIdx.x*(KNN_WARPS*KNN_QB) + warp*KNN_QB;
    unsigned long long* bufw = wbuf + (size_t)warp*KNN_QB*KNN_BUF;

    unsigned long long qx2[KNN_QB/2], qy2[KNN_QB/2], qz2[KNN_QB/2];
    #pragma unroll
    for (int jp = 0; jp < KNN_QB/2; jp++) {
        float4 Qa = cand[qbase + 2*jp];
        float4 Qb = cand[qbase + 2*jp + 1];
        qx2[jp] = packxy(-2.f*Qa.x, -2.f*Qb.x);
        qy2[jp] = packxy(-2.f*Qa.y, -2.f*Qb.y);
        qz2[jp] = packxy(-2.f*Qa.z, -2.f*Qb.z);
    }

    float lmin[KNN_QB];
    #pragma unroll
    for (int j = 0; j < KNN_QB; j++) lmin[j] = 3.4e38f;
    for (int m = lane; m < 4096; m += 32) {
        float4 c = cand[m];
        unsigned long long cx2 = pack2(c.x), cy2 = pack2(c.y),
                           cz2 = pack2(c.z), cw2 = pack2(c.w);
        #pragma unroll
        for (int jp = 0; jp < KNN_QB/2; jp++) {
            unsigned long long k2 = ffma2(cx2, qx2[jp],
                                    ffma2(cy2, qy2[jp],
                                    ffma2(cz2, qz2[jp], cw2)));
            float klo, khi; unpack2(k2, klo, khi);
            lmin[2*jp]   = fminf(lmin[2*jp],   klo);
            lmin[2*jp+1] = fminf(lmin[2*jp+1], khi);
        }
    }

    float tau[KNN_QB];
    #pragma unroll
    for (int j = 0; j < KNN_QB; j++) {
        float val = lmin[j], t = 0.f;
        #pragma unroll
        for (int r = 0; r < 11; r++) {
            float mn = val;
            #pragma unroll
            for (int off = 16; off; off >>= 1)
                mn = fminf(mn, __shfl_xor_sync(FULLMASK, mn, off));
            t = mn;
            unsigned bal = __ballot_sync(FULLMASK, val == mn);
            if (lane == __ffs(bal) - 1) val = 3.4e38f;
        }
        tau[j] = t;
    }

    if (lane < KNN_QB) scnt[warp][lane] = 0;
    __syncwarp();
    for (int m = lane; m < 4096; m += 32) {
        float4 c = cand[m];
        unsigned long long cx2 = pack2(c.x), cy2 = pack2(c.y),
                           cz2 = pack2(c.z), cw2 = pack2(c.w);
        #pragma unroll
        for (int jp = 0; jp < KNN_QB/2; jp++) {
            unsigned long long k2 = ffma2(cx2, qx2[jp],
                                    ffma2(cy2, qy2[jp],
                                    ffma2(cz2, qz2[jp], cw2)));
            float klo, khi; unpack2(k2, klo, khi);
            if (klo <= tau[2*jp]) {
                int pos = atomicAdd(&scnt[warp][2*jp], 1);
                if (pos < KNN_BUF)
                    bufw[(2*jp)*KNN_BUF + pos] =
                        ((unsigned long long)orderable_f32(klo) << 32) | (unsigned)m;
            }
            if (khi <= tau[2*jp+1]) {
                int pos = atomicAdd(&scnt[warp][2*jp+1], 1);
                if (pos < KNN_BUF)
                    bufw[(2*jp+1)*KNN_BUF + pos] =
                        ((unsigned long long)orderable_f32(khi) << 32) | (unsigned)m;
            }
        }
    }
    __syncwarp();

    #pragma unroll
    for (int j = 0; j < KNN_QB; j++) {
        const int q = qbase + j;
        const int cj = scnt[warp][j];
        if (cj <= KNN_BUF) {
            unsigned long long v0, v1;
            v0 = (lane      < cj) ? bufw[j*KNN_BUF + lane]      : 0xffffffffffffffffull;
            v1 = (lane + 32 < cj) ? bufw[j*KNN_BUF + lane + 32] : 0xffffffffffffffffull;
            #pragma unroll
            for (int r = 0; r < 11; r++) {
                unsigned long long mn = min(v0, v1);
                #pragma unroll
                for (int off = 16; off; off >>= 1) {
                    unsigned long long o = __shfl_xor_sync(FULLMASK, mn, off);
                    if (o < mn) mn = o;
                }
                if (v0 == mn) v0 = 0xffffffffffffffffull;
                if (v1 == mn) v1 = 0xffffffffffffffffull;
                if (lane == 0)
                    nbr[((size_t)b*4096 + q)*11 + r] = b*4096 + (int)(mn & 0xffffffffu);
            }
        } else {
            float4 Q = cand[q];
            float m2x = -2.f*Q.x, m2y = -2.f*Q.y, m2z = -2.f*Q.z;
            unsigned long long last = 0ull;
            for (int r = 0; r < 11; r++) {
                unsigned long long lm = 0xffffffffffffffffull;
                for (int m = lane; m < 4096; m += 32) {
                    float4 c = cand[m];
                    float key = fmaf(c.x, m2x, fmaf(c.y, m2y, fmaf(c.z, m2z, c.w)));
                    unsigned long long pk =
                        ((unsigned long long)orderable_f32(key) << 32) | (unsigned)m;
                    if (pk > last && pk < lm) lm = pk;
                }
                unsigned long long mn = lm;
                #pragma unroll
                for (int off = 16; off; off >>= 1) {
                    unsigned long long o = __shfl_xor_sync(FULLMASK, mn, off);
                    if (o < mn) mn = o;
                }
                last = mn;
                if (lane == 0)
                    nbr[((size_t)b*4096 + q)*11 + r] = b*4096 + (int)(mn & 0xffffffffu);
            }
        }
    }
}

// ---------------- stage-1 u/v + W2 transpose/split + stats-zero ----------------
__global__ void uv1p_kernel(const float* __restrict__ x, const float* __restrict__ W1,
                            float* __restrict__ buf1,
                            const float* __restrict__ W2, const float* __restrict__ Ws2a,
                            __nv_bfloat16* __restrict__ W2t_h, __nv_bfloat16* __restrict__ W2t_l,
                            float* __restrict__ stats)
{
    int idx = blockIdx.x*blockDim.x + threadIdx.x;
    if (idx < 3*512) stats[idx] = 0.f;
    if (idx < 384*64) {
        int n = idx/64, k = idx%64;
        float v;
        if      (n < 128) v = W2[k*128 + n];
        else if (n < 256) v = W2[(64+k)*128 + (n-128)];
        else if (n < 320) v = Ws2a[k*64 + (n-256)];
        else              v = Ws2a[(64+k)*64 + (n-320)];
        __nv_bfloat16 h, l; bsplit(v, h, l);
        W2t_h[idx] = h; W2t_l[idx] = l;
    }
    if (idx >= BNPTS*64) return;
    int n = idx >> 6, c = idx & 63;
    const float* xp = x + (size_t)n*5;
    float x0 = xp[0], x1 = xp[1], x2 = xp[2], x3 = xp[3], x4 = xp[4];
    float u = x0*W1[0*64+c] + x1*W1[1*64+c] + x2*W1[2*64+c] + x3*W1[6*64+c] + x4*W1[7*64+c];
    float v = x0*W1[3*64+c] + x1*W1[4*64+c] + x2*W1[5*64+c] + x3*W1[8*64+c] + x4*W1[9*64+c];
    buf1[n*128 + c]      = u;
    buf1[n*128 + 64 + c] = v;
}

// ---------------- prep3a: Wa1 transpose/split + pooled zero ----------------
__global__ void prep3a_kernel(const float* __restrict__ Wa1,
                              __nv_bfloat16* __restrict__ Wa1t_h,
                              __nv_bfloat16* __restrict__ Wa1t_l,
                              float* __restrict__ pooled)
{
    int j = blockIdx.x*blockDim.x + threadIdx.x;
    if (j < BB*256) pooled[j] = 0.f;
    if (j < 64*256) {
        int n = j/256, k = j%256;
        __nv_bfloat16 h, l; bsplit(Wa1[k*64 + n], h, l);
        Wa1t_h[j] = h; Wa1t_l[j] = l;
    }
}

// ---------------- prep3b: W3 transpose/split ----------------
__global__ void prep3b_kernel(const float* __restrict__ W3, const float* __restrict__ Ws3a,
                              __nv_bfloat16* __restrict__ W3t_h,
                              __nv_bfloat16* __restrict__ W3t_l)
{
    int j = blockIdx.x*blockDim.x + threadIdx.x;
    if (j < 768*128) {
        int n = j/128, k = j%128;
        float v;
        if      (n < 256) v = W3[k*256 + n];
        else if (n < 512) v = W3[(128+k)*256 + (n-256)];
        else if (n < 640) v = Ws3a[k*128 + (n-512)];
        else              v = Ws3a[(128+k)*128 + (n-640)];
        __nv_bfloat16 h, l; bsplit(v, h, l);
        W3t_h[j] = h; W3t_l[j] = l;
    }
}

// ---------------- BN statistics: compile-time PPB, 2x point interleave --------
template<int C, int PPB, bool MAXOUT>
__global__ void stats_kernel(const float* __restrict__ buf, int stride, int uoff, int voff,
                             const int* __restrict__ nbr, int koff,
                             float* __restrict__ stats, float* __restrict__ maxOut,
                             const float* __restrict__ g, const float* __restrict__ bbias,
                             float* __restrict__ scale, float* __restrict__ shift,
                             unsigned* __restrict__ ctr)
{
    const int c = threadIdx.x;
    const int p0 = blockIdx.x * PPB;
    float sum = 0.f, ss = 0.f;
    #pragma unroll 2
    for (int p = 0; p < PPB; p++) {
        int n = p0 + p;
        float un = buf[(size_t)n*stride + uoff + c];
        float vn = buf[(size_t)n*stride + voff + c];
        float w = vn - un;
        float mx = -3.4e38f;
        #pragma unroll
        for (int k = 0; k < KK; k++) {
            int j = nbr[n*11 + koff + k];
            float z = buf[(size_t)j*stride + uoff + c] + w;
            sum += z; ss += z*z;
            mx = fmaxf(mx, z);
        }
        if (MAXOUT) maxOut[(size_t)n*C + c] = mx;
    }
    atomicAdd(&stats[c], sum);
    atomicAdd(&stats[256 + c], ss);

    __threadfence();
    __shared__ unsigned done;
    if (c == 0) done = atomicAdd(ctr, 1u);
    __syncthreads();
    if (done == gridDim.x - 1) {
        float mean = stats[c] / EDGE_COUNT;
        float var  = stats[256 + c] / EDGE_COUNT - mean*mean;
        float rs = rsqrtf(var + EPS);
        float sc = g[c]*rs;
        scale[c] = sc;
        shift[c] = bbias[c] - mean*sc;
        if (c == 0) *ctr = 0;
    }
}

// ---------------- tensor GEMM: split-bf16 mma.sync, double-buffered ----------
#define AROW 48   // smem row stride bytes (16 bf16 = 32B data + 16B pad)

template<int BM, int BN, int NT, bool FUSEA>
__global__ __launch_bounds__(NT) void tgemm_kernel(
    const float* __restrict__ A,
    const __nv_bfloat16* __restrict__ Bh, const __nv_bfloat16* __restrict__ Bl,
    float* __restrict__ C, int M, int N, int Kd,
    const float* __restrict__ fscale, const float* __restrict__ fshift)
{
    constexpr int NWARP = NT/32;
    constexpr int WC = BN/32;
    constexpr int WR = BM/32;
    static_assert(WR*WC == NWARP, "warp grid mismatch");
    constexpr int ALD = (BM*16)/(4*NT);

    __shared__ __align__(16) unsigned char Ash[2][2][BM*AROW];
    __shared__ __align__(16) unsigned char Bsh[2][2][BN*AROW];

    const int tid  = threadIdx.x;
    const int warp = tid >> 5, lane = tid & 31;
    const int wr = warp / WC, wc = warp % WC;
    const int rowBase = blockIdx.x*BM, colBase = blockIdx.y*BN;

    float acc[2][4][4];
    #pragma unroll
    for (int m = 0; m < 2; m++)
        #pragma unroll
        for (int j = 0; j < 4; j++)
            #pragma unroll
            for (int r = 0; r < 4; r++) acc[m][j][r] = 0.f;

    float4 aReg[ALD];
    uint4 bRegH, bRegL;
    const bool bAct = (BN == 128) || (tid < BN*2);
    const int bn = tid >> 1, bhalf = tid & 1;

    auto LDG = [&](int k0) {
        #pragma unroll
        for (int l = 0; l < ALD; l++) {
            int i = tid + l*NT;
            int r = i >> 2, kk = (i & 3)*4;
            float4 v = *reinterpret_cast<const float4*>(
                &A[(size_t)(rowBase + r)*Kd + k0 + kk]);
            if (FUSEA) {
                float4 sc = *reinterpret_cast<const float4*>(&fscale[k0 + kk]);
                float4 sh = *reinterpret_cast<const float4*>(&fshift[k0 + kk]);
                v.x = fmaxf(fmaf(sc.x, v.x, sh.x), 0.f);
                v.y = fmaxf(fmaf(sc.y, v.y, sh.y), 0.f);
                v.z = fmaxf(fmaf(sc.z, v.z, sh.z), 0.f);
                v.w = fmaxf(fmaf(sc.w, v.w, sh.w), 0.f);
            }
            aReg[l] = v;
        }
        if (bAct) {
            size_t off = (size_t)(colBase + bn)*Kd + k0 + bhalf*8;
            bRegH = *reinterpret_cast<const uint4*>(Bh + off);
            bRegL = *reinterpret_cast<const uint4*>(Bl + off);
        }
    };
    auto STS = [&](int bf) {
        #pragma unroll
        for (int l = 0; l < ALD; l++) {
            int i = tid + l*NT;
            int r = i >> 2, kk = (i & 3)*4;
            float4 v = aReg[l];
            __nv_bfloat16 hx, lx, hy, ly, hz, lz, hw, lw;
            bsplit(v.x, hx, lx); bsplit(v.y, hy, ly);
            bsplit(v.z, hz, lz); bsplit(v.w, hw, lw);
            unsigned long long hword =
                (unsigned long long)bfpair(hx, hy)
                | ((unsigned long long)bfpair(hz, hw) << 32);
            unsigned long long lword =
                (unsigned long long)bfpair(lx, ly)
                | ((unsigned long long)bfpair(lz, lw) << 32);
            int boff = r*AROW + kk*2;
            *reinterpret_cast<unsigned long long*>(&Ash[bf][0][boff]) = hword;
            *reinterpret_cast<unsigned long long*>(&Ash[bf][1][boff]) = lword;
        }
        if (bAct) {
            int boff = bn*AROW + bhalf*16;
            *reinterpret_cast<uint4*>(&Bsh[bf][0][boff]) = bRegH;
            *reinterpret_cast<uint4*>(&Bsh[bf][1][boff]) = bRegL;
        }
    };
    auto COMPUTE = [&](int bf) {
        unsigned a[2][2][4];
        const int arow = (lane & 7) + ((lane >> 3) & 1)*8;
        const int akh  = lane >> 4;
        #pragma unroll
        for (int mi = 0; mi < 2; mi++)
            #pragma unroll
            for (int h = 0; h < 2; h++)
                ldsm4(a[mi][h][0], a[mi][h][1], a[mi][h][2], a[mi][h][3],
                      smem_u32(&Ash[bf][h][(wr*32 + mi*16 + arow)*AROW + akh*16]));
        unsigned b[2][4][2];
        const int brow = (lane & 7) + ((lane >> 4) & 1)*8;
        const int bkh  = (lane >> 3) & 1;
        #pragma unroll
        for (int bj = 0; bj < 2; bj++)
            #pragma unroll
            for (int h = 0; h < 2; h++) {
                unsigned t0, t1, t2, t3;
                ldsm4(t0, t1, t2, t3,
                      smem_u32(&Bsh[bf][h][(wc*32 + bj*16 + brow)*AROW + bkh*16]));
                b[h][bj*2+0][0] = t0; b[h][bj*2+0][1] = t1;
                b[h][bj*2+1][0] = t2; b[h][bj*2+1][1] = t3;
            }
        #pragma unroll
        for (int mi = 0; mi < 2; mi++)
            #pragma unroll
            for (int j = 0; j < 4; j++) {
                mma_bf16(acc[mi][j], a[mi][0], b[0][j]);
                mma_bf16(acc[mi][j], a[mi][0], b[1][j]);
                mma_bf16(acc[mi][j], a[mi][1], b[0][j]);
            }
    };

    const int nch = Kd / 16;
    LDG(0);
    STS(0);
    __syncthreads();
    for (int c = 0; c < nch; c++) {
        int cur = c & 1;
        if (c + 1 < nch) LDG((c + 1)*16);
        COMPUTE(cur);
        if (c + 1 < nch) STS(cur ^ 1);
        __syncthreads();
    }

    #pragma unroll
    for (int mi = 0; mi < 2; mi++)
        #pragma unroll
        for (int j = 0; j < 4; j++) {
            int row0 = rowBase + wr*32 + mi*16 + (lane >> 2);
            int col  = colBase + wc*32 + j*8 + (lane & 3)*2;
            float2 p0; p0.x = acc[mi][j][0]; p0.y = acc[mi][j][1];
            float2 p1; p1.x = acc[mi][j][2]; p1.y = acc[mi][j][3];
            *reinterpret_cast<float2*>(&C[(size_t)row0*N + col]) = p0;
            *reinterpret_cast<float2*>(&C[(size_t)(row0 + 8)*N + col]) = p1;
        }
}

// ---------------- soft-edge aggregation (parallel softmax) ----------------
template<int C, int CA>
__global__ void softedge_kernel(const float* __restrict__ buf, const int* __restrict__ nbr,
                                const float* __restrict__ scale, const float* __restrict__ shift,
                                const float* __restrict__ ab,
                                const float* __restrict__ Wb, const float* __restrict__ bb,
                                float* __restrict__ fout)
{
    constexpr int STRIDE = 2*C + 2*CA;
    constexpr int AOFF = 2*C;
    const int n = blockIdx.x;
    const int t = threadIdx.x;

    __shared__ int   js[KK];
    __shared__ float wps[KK][C/32];
    __shared__ float alpha[KK];

    if (t < KK) js[t] = nbr[n*11 + 1 + t];
    __syncthreads();

    float base_a = 0.f;
    if (t < CA) {
        float usn = buf[(size_t)n*STRIDE + AOFF + t];
        base_a = buf[(size_t)n*STRIDE + AOFF + CA + t] - usn + ab[t];
    }
    #pragma unroll
    for (int k = 0; k < KK; k++) {
        float v = 0.f;
        if (t < CA) {
            float h = buf[(size_t)js[k]*STRIDE + AOFF + t] + base_a;
            h = fmaxf(h, 0.f);
            v = h * Wb[t];
        }
        #pragma unroll
        for (int off = 16; off; off >>= 1) v += __shfl_down_sync(FULLMASK, v, off);
        if ((t & 31) == 0) wps[k][t >> 5] = v;
    }
    __syncthreads();
    if (t < KK) {
        float s = 0.f;
        #pragma unroll
        for (int w = 0; w < C/32; w++) s += wps[t][w];
        alpha[t] = (s + bb[0]) / TAU;
    }
    __syncthreads();
    if (t < 32) {
        float v = (t < KK) ? alpha[t] : -3.4e38f;
        float mx = v;
        #pragma unroll
        for (int off = 16; off; off >>= 1)
            mx = fmaxf(mx, __shfl_xor_sync(FULLMASK, mx, off));
        float e = (t < KK) ? expf(v - mx) : 0.f;
        float s = e;
        #pragma unroll
        for (int off = 16; off; off >>= 1) s += __shfl_xor_sync(FULLMASK, s, off);
        if (t < KK) alpha[t] = e / s;
    }
    __syncthreads();

    float un = buf[(size_t)n*STRIDE + t];
    float w  = buf[(size_t)n*STRIDE + C + t] - un;
    float sc = scale[t], sh = shift[t];
    float acc = 0.f;
    #pragma unroll
    for (int k = 0; k < KK; k++) {
        float z = buf[(size_t)js[k]*STRIDE + t] + w;
        acc += alpha[k] * fmaxf(sc*z + sh, 0.f);
    }
    fout[(size_t)n*C + t] = acc;
}

// ---------------- final attention pooling ----------------
__global__ void wlog_kernel(const float* __restrict__ hall, const float* __restrict__ ba1,
                            const float* __restrict__ Wa2, const float* __restrict__ ba2,
                            float* __restrict__ wlog)
{
    int gw = (blockIdx.x*blockDim.x + threadIdx.x) >> 5;
    int lane = threadIdx.x & 31;
    if (gw >= BNPTS) return;
    float acc = 0.f;
    #pragma unroll
    for (int h = 0; h < 2; h++) {
        int c = lane + 32*h;
        float v = fmaxf(hall[(size_t)gw*64 + c] + ba1[c], 0.f);
        acc += v * Wa2[c];
    }
    #pragma unroll
    for (int off = 16; off; off >>= 1) acc += __shfl_down_sync(FULLMASK, acc, off);
    if (lane == 0) wlog[gw] = acc + ba2[0];
}

__global__ void batred_kernel(const float* __restrict__ wlog, float* __restrict__ bmax,
                              float* __restrict__ bsum)
{
    int b = blockIdx.x, t = threadIdx.x;
    __shared__ float red[256];
    float mx = -3.4e38f;
    for (int n = t; n < NN; n += 256) mx = fmaxf(mx, wlog[b*NN + n]);
    red[t] = mx; __syncthreads();
    for (int s = 128; s; s >>= 1) { if (t < s) red[t] = fmaxf(red[t], red[t+s]); __syncthreads(); }
    float M = red[0]; __syncthreads();
    float s = 0.f;
    for (int n = t; n < NN; n += 256) s += expf(wlog[b*NN + n] - M);
    red[t] = s; __syncthreads();
    for (int st = 128; st; st >>= 1) { if (t < st) red[t] += red[t+st]; __syncthreads(); }
    if (t == 0) { bmax[b] = M; bsum[b] = red[0]; }
}

__global__ void pool_kernel(const float* __restrict__ f3, const float* __restrict__ wlog,
                            const float* __restrict__ bmax, const float* __restrict__ bsum,
                            float* __restrict__ pooled)
{
    int b = blockIdx.y, t = threadIdx.x;
    int n0 = blockIdx.x * 256;
    __shared__ float ew[256];
    ew[t] = expf(wlog[b*NN + n0 + t] - bmax[b]) / bsum[b];
    __syncthreads();
    float acc = 0.f;
    for (int i = 0; i < 256; i++)
        acc += ew[i] * f3[((size_t)b*NN + n0 + i)*256 + t];
    atomicAdd(&pooled[b*256 + t], acc);
}

__global__ void final_kernel(const float* __restrict__ pooled, const float* __restrict__ Wfc,
                             const float* __restrict__ bfc, float* __restrict__ out)
{
    int b = blockIdx.x, t = threadIdx.x;
    __shared__ float p[256];
    p[t] = pooled[b*256 + t];
    __syncthreads();
    float acc = bfc[t];
    for (int i = 0; i < 256; i++) acc = fmaf(p[i], Wfc[i*256 + t], acc);
    out[b*256 + t] = fmaxf(acc, 0.f);
}

// ---------------- host launcher ----------------
static void* sym_addr_helper(const void* symbol)
{
    void* p = nullptr;
    cudaGetSymbolAddress(&p, symbol);
    return p;
}

extern "C" void kernel_launch(void* const* d_in, const int* in_sizes, int n_in,
                              void* d_out, int out_size)
{
    const float* x    = (const float*)d_in[0];
    const float* W1   = (const float*)d_in[1];
    const float* g1   = (const float*)d_in[2];
    const float* b1   = (const float*)d_in[3];
    const float* W2   = (const float*)d_in[4];
    const float* g2   = (const float*)d_in[5];
    const float* b2   = (const float*)d_in[6];
    const float* Ws2a = (const float*)d_in[7];
    const float* bs2a = (const float*)d_in[8];
    const float* Ws2b = (const float*)d_in[9];
    const float* bs2b = (const float*)d_in[10];
    const float* W3   = (const float*)d_in[11];
    const float* g3   = (const float*)d_in[12];
    const float* b3   = (const float*)d_in[13];
    const float* Ws3a = (const float*)d_in[14];
    const float* bs3a = (const float*)d_in[15];
    const float* Ws3b = (const float*)d_in[16];
    const float* bs3b = (const float*)d_in[17];
    const float* Wa1  = (const float*)d_in[18];
    const float* ba1  = (const float*)d_in[19];
    const float* Wa2  = (const float*)d_in[20];
    const float* ba2  = (const float*)d_in[21];
    const float* Wfc  = (const float*)d_in[22];
    const float* bfc  = (const float*)d_in[23];
    float* out = (float*)d_out;
    (void)in_sizes; (void)n_in; (void)out_size;

    int*      nbr    = (int*)     sym_addr_helper(d_nbr);
    float*    buf1   = (float*)   sym_addr_helper(d_buf1);
    float*    m1     = (float*)   sym_addr_helper(d_m1);
    float*    buf2   = (float*)   sym_addr_helper(d_buf2);
    float*    f2     = (float*)   sym_addr_helper(d_f2);
    float*    buf3   = (float*)   sym_addr_helper(d_buf3);
    float*    f3     = (float*)   sym_addr_helper(d_f3);
    float*    hall   = (float*)   sym_addr_helper(d_hall);
    __nv_bfloat16* W2t_h  = (__nv_bfloat16*)sym_addr_helper(d_W2t_h);
    __nv_bfloat16* W2t_l  = (__nv_bfloat16*)sym_addr_helper(d_W2t_l);
    __nv_bfloat16* W3t_h  = (__nv_bfloat16*)sym_addr_helper(d_W3t_h);
    __nv_bfloat16* W3t_l  = (__nv_bfloat16*)sym_addr_helper(d_W3t_l);
    __nv_bfloat16* Wa1t_h = (__nv_bfloat16*)sym_addr_helper(d_Wa1t_h);
    __nv_bfloat16* Wa1t_l = (__nv_bfloat16*)sym_addr_helper(d_Wa1t_l);
    float*    stats  = (float*)   sym_addr_helper(d_stats);
    float*    scale  = (float*)   sym_addr_helper(d_scale);
    float*    shift  = (float*)   sym_addr_helper(d_shift);
    unsigned* ctr    = (unsigned*)sym_addr_helper(d_ctr);
    float*    wlog   = (float*)   sym_addr_helper(d_wlog);
    float*    bmax   = (float*)   sym_addr_helper(d_bmax);
    float*    bsum   = (float*)   sym_addr_helper(d_bsum);
    float*    pooled = (float*)   sym_addr_helper(d_pooled);

    cudaFuncSetAttribute(knn_kernel, cudaFuncAttributeMaxDynamicSharedMemorySize, KNN_SMEM);

    // launch order: uv1p(1), prep3a(2), prep3b(3), knn(4) <- ncu capture slot
    uv1p_kernel<<<BNPTS*64/256, 256>>>(x, W1, buf1, W2, Ws2a, W2t_h, W2t_l, stats);
    prep3a_kernel<<<(64*256 + 255)/256, 256>>>(Wa1, Wa1t_h, Wa1t_l, pooled);
    prep3b_kernel<<<(768*128 + 255)/256, 256>>>(W3, Ws3a, W3t_h, W3t_l);
    knn_kernel<<<dim3(4096/(KNN_WARPS*KNN_QB), BB), KNN_WARPS*32, KNN_SMEM>>>(x, nbr);

    // stage 1 (finalize fused into stats; f1 fused into gemm2's A-load)
    stats_kernel<64,16,true><<<BNPTS/16, 64>>>(buf1, 128, 0, 64, nbr, 0, stats, m1,
                                               g1, b1, scale, shift, ctr);

    // stage 2 (tensor GEMM)
    tgemm_kernel<64,128,256,true><<<dim3(BNPTS/64, 3), 256>>>(
        m1, W2t_h, W2t_l, buf2, BNPTS, 384, 64, scale, shift);
    stats_kernel<128,16,false><<<BNPTS/16, 128>>>(buf2, 384, 0, 128, nbr, 1, stats + 512,
                                                  nullptr, g2, b2, scale + 256, shift + 256,
                                                  ctr + 1);
    softedge_kernel<128,64><<<BNPTS, 128>>>(buf2, nbr, scale + 256, shift + 256, bs2a, Ws2b, bs2b, f2);

    // stage 3 (tensor GEMM)
    tgemm_kernel<64,128,256,false><<<dim3(BNPTS/64, 6), 256>>>(
        f2, W3t_h, W3t_l, buf3, BNPTS, 768, 128, nullptr, nullptr);
    stats_kernel<256,8,false><<<BNPTS/8, 256>>>(buf3, 768, 0, 256, nbr, 1, stats + 1024,
                                                nullptr, g3, b3, scale + 512, shift + 512,
                                                ctr + 2);
    softedge_kernel<256,128><<<BNPTS, 256>>>(buf3, nbr, scale + 512, shift + 512, bs3a, Ws3b, bs3b, f3);

    // attention pooling + head (tensor GEMM for hall)
    tgemm_kernel<128,64,256,false><<<dim3(BNPTS/128, 1), 256>>>(
        f3, Wa1t_h, Wa1t_l, hall, BNPTS, 64, 256, nullptr, nullptr);
    wlog_kernel<<<BNPTS/8, 256>>>(hall, ba1, Wa2, ba2, wlog);
    batred_kernel<<<BB, 256>>>(wlog, bmax, bsum);
    pool_kernel<<<dim3(NN/256, BB), 256>>>(f3, wlog, bmax, bsum, pooled);
    final_kernel<<<BB, 256>>>(pooled, Wfc, bfc, out);
}

// round 17
// speedup vs baseline: 1.0311x; 1.0311x over previous
#include <cuda_runtime.h>
#include <cuda_bf16.h>
#include <cstdint>

#define BB 8
#define NN 4096
#define KK 10
#define BNPTS (BB*NN)          // 32768
#define EDGE_COUNT 327680.0f   // B*N*K
#define TAU 0.2f
#define EPS 1e-5f
#define FULLMASK 0xffffffffu

// ---------------- device scratch (no allocations allowed) ----------------
__device__ int   d_nbr[BNPTS*11];
__device__ float d_buf1[BNPTS*128];     // u1(64)|v1(64)
__device__ float d_m1[BNPTS*64];        // max_k z (stage1)
__device__ float d_buf2[BNPTS*384];     // u2(128)|v2(128)|us2(64)|vs2(64)
__device__ float d_f2[BNPTS*128];
__device__ float d_buf3[BNPTS*768];     // u3(256)|v3(256)|us3(128)|vs3(128)
__device__ float d_f3[BNPTS*256];
__device__ __nv_bfloat16 d_W2t_h[384*64],  d_W2t_l[384*64];    // [N][K] split
__device__ __nv_bfloat16 d_W3t_h[768*128], d_W3t_l[768*128];
__device__ __nv_bfloat16 d_Wa1t_h[64*256], d_Wa1t_l[64*256];
__device__ float d_stats[3*512];
__device__ __align__(16) float d_scale[3*256];
__device__ __align__(16) float d_shift[3*256];
__device__ unsigned d_ctr[3];
__device__ float d_wlog[BNPTS];
__device__ float d_bmax[BB];
__device__ float d_bsum[BB];
__device__ float d_pooled[BB*256];

// ---------------- packed f32x2 helpers (knn) ----------------
__device__ __forceinline__ unsigned long long ffma2(unsigned long long a,
                                                    unsigned long long b,
                                                    unsigned long long c)
{
    unsigned long long d;
    asm("fma.rn.f32x2 %0, %1, %2, %3;" : "=l"(d) : "l"(a), "l"(b), "l"(c));
    return d;
}
__device__ __forceinline__ unsigned long long pack2(float x)
{
    unsigned long long d;
    asm("mov.b64 %0, {%1, %1};" : "=l"(d) : "r"(__float_as_uint(x)));
    return d;
}
__device__ __forceinline__ unsigned long long packxy(float x, float y)
{
    unsigned long long d;
    asm("mov.b64 %0, {%1, %2};" : "=l"(d)
        : "r"(__float_as_uint(x)), "r"(__float_as_uint(y)));
    return d;
}
__device__ __forceinline__ void unpack2(unsigned long long v, float& lo, float& hi)
{
    unsigned int a, b;
    asm("mov.b64 {%0, %1}, %2;" : "=r"(a), "=r"(b) : "l"(v));
    lo = __uint_as_float(a); hi = __uint_as_float(b);
}

// ---------------- tensor helpers ----------------
__device__ __forceinline__ unsigned smem_u32(const void* p)
{
    return (unsigned)__cvta_generic_to_shared(p);
}
__device__ __forceinline__ void ldsm4(unsigned& r0, unsigned& r1,
                                      unsigned& r2, unsigned& r3, unsigned a)
{
    asm volatile("ldmatrix.sync.aligned.m8n8.x4.shared.b16 {%0,%1,%2,%3}, [%4];"
        : "=r"(r0), "=r"(r1), "=r"(r2), "=r"(r3) : "r"(a));
}
__device__ __forceinline__ void mma_bf16(float* c, const unsigned* a, const unsigned* b)
{
    asm volatile("mma.sync.aligned.m16n8k16.row.col.f32.bf16.bf16.f32 "
        "{%0,%1,%2,%3}, {%4,%5,%6,%7}, {%8,%9}, {%0,%1,%2,%3};"
        : "+f"(c[0]), "+f"(c[1]), "+f"(c[2]), "+f"(c[3])
        : "r"(a[0]), "r"(a[1]), "r"(a[2]), "r"(a[3]), "r"(b[0]), "r"(b[1]));
}
__device__ __forceinline__ void bsplit(float v, __nv_bfloat16& h, __nv_bfloat16& l)
{
    h = __float2bfloat16_rn(v);
    l = __float2bfloat16_rn(v - __bfloat162float(h));
}
__device__ __forceinline__ unsigned bfpair(__nv_bfloat16 a, __nv_bfloat16 b)
{
    return (unsigned)__bfloat16_as_ushort(a)
         | ((unsigned)__bfloat16_as_ushort(b) << 16);
}

// ---------------- KNN: threshold-filter top-11 (proven 652us config) ---------
#define KNN_WARPS 8
#define KNN_QB 8
#define KNN_BUF 64
#define KNN_SMEM (4096*16 + KNN_WARPS*KNN_QB*KNN_BUF*8)

__device__ __forceinline__ unsigned orderable_f32(float f)
{
    unsigned u = __float_as_uint(f);
    return (u & 0x80000000u) ? ~u : (u | 0x80000000u);
}

__global__ __launch_bounds__(KNN_WARPS*32) void knn_kernel(
    const float* __restrict__ x, int* __restrict__ nbr)
{
    extern __shared__ unsigned char smem_raw[];
    float4* cand = (float4*)smem_raw;
    unsigned long long* wbuf = (unsigned long long*)(cand + 4096);
    __shared__ int scnt[KNN_WARPS][KNN_QB];

    const int b    = blockIdx.y;
    const int tid  = threadIdx.x;
    const int warp = tid >> 5;
    const int lane = tid & 31;

    for (int i = tid; i < 4096; i += blockDim.x) {
        const float* xp = x + ((size_t)b*4096 + i)*5;
        float cx = xp[0], cy = xp[1], cz = xp[2];
        cand[i] = make_float4(cx, cy, cz, cx*cx + cy*cy + cz*cz);
    }
    __syncthreads();

    const int qbase = blockIdx.x*(KNN_WARPS*KNN_QB) + warp*KNN_QB;
    unsigned long long* bufw = wbuf + (size_t)warp*KNN_QB*KNN_BUF;

    unsigned long long qx2[KNN_QB/2], qy2[KNN_QB/2], qz2[KNN_QB/2];
    #pragma unroll
    for (int jp = 0; jp < KNN_QB/2; jp++) {
        float4 Qa = cand[qbase + 2*jp];
        float4 Qb = cand[qbase + 2*jp + 1];
        qx2[jp] = packxy(-2.f*Qa.x, -2.f*Qb.x);
        qy2[jp] = packxy(-2.f*Qa.y, -2.f*Qb.y);
        qz2[jp] = packxy(-2.f*Qa.z, -2.f*Qb.z);
    }

    float lmin[KNN_QB];
    #pragma unroll
    for (int j = 0; j < KNN_QB; j++) lmin[j] = 3.4e38f;
    for (int m = lane; m < 4096; m += 32) {
        float4 c = cand[m];
        unsigned long long cx2 = pack2(c.x), cy2 = pack2(c.y),
                           cz2 = pack2(c.z), cw2 = pack2(c.w);
        #pragma unroll
        for (int jp = 0; jp < KNN_QB/2; jp++) {
            unsigned long long k2 = ffma2(cx2, qx2[jp],
                                    ffma2(cy2, qy2[jp],
                                    ffma2(cz2, qz2[jp], cw2)));
            float klo, khi; unpack2(k2, klo, khi);
            lmin[2*jp]   = fminf(lmin[2*jp],   klo);
            lmin[2*jp+1] = fminf(lmin[2*jp+1], khi);
        }
    }

    float tau[KNN_QB];
    #pragma unroll
    for (int j = 0; j < KNN_QB; j++) {
        float val = lmin[j], t = 0.f;
        #pragma unroll
        for (int r = 0; r < 11; r++) {
            float mn = val;
            #pragma unroll
            for (int off = 16; off; off >>= 1)
                mn = fminf(mn, __shfl_xor_sync(FULLMASK, mn, off));
            t = mn;
            unsigned bal = __ballot_sync(FULLMASK, val == mn);
            if (lane == __ffs(bal) - 1) val = 3.4e38f;
        }
        tau[j] = t;
    }

    if (lane < KNN_QB) scnt[warp][lane] = 0;
    __syncwarp();
    for (int m = lane; m < 4096; m += 32) {
        float4 c = cand[m];
        unsigned long long cx2 = pack2(c.x), cy2 = pack2(c.y),
                           cz2 = pack2(c.z), cw2 = pack2(c.w);
        #pragma unroll
        for (int jp = 0; jp < KNN_QB/2; jp++) {
            unsigned long long k2 = ffma2(cx2, qx2[jp],
                                    ffma2(cy2, qy2[jp],
                                    ffma2(cz2, qz2[jp], cw2)));
            float klo, khi; unpack2(k2, klo, khi);
            if (klo <= tau[2*jp]) {
                int pos = atomicAdd(&scnt[warp][2*jp], 1);
                if (pos < KNN_BUF)
                    bufw[(2*jp)*KNN_BUF + pos] =
                        ((unsigned long long)orderable_f32(klo) << 32) | (unsigned)m;
            }
            if (khi <= tau[2*jp+1]) {
                int pos = atomicAdd(&scnt[warp][2*jp+1], 1);
                if (pos < KNN_BUF)
                    bufw[(2*jp+1)*KNN_BUF + pos] =
                        ((unsigned long long)orderable_f32(khi) << 32) | (unsigned)m;
            }
        }
    }
    __syncwarp();

    #pragma unroll
    for (int j = 0; j < KNN_QB; j++) {
        const int q = qbase + j;
        const int cj = scnt[warp][j];
        if (cj <= KNN_BUF) {
            unsigned long long v0, v1;
            v0 = (lane      < cj) ? bufw[j*KNN_BUF + lane]      : 0xffffffffffffffffull;
            v1 = (lane + 32 < cj) ? bufw[j*KNN_BUF + lane + 32] : 0xffffffffffffffffull;
            #pragma unroll
            for (int r = 0; r < 11; r++) {
                unsigned long long mn = min(v0, v1);
                #pragma unroll
                for (int off = 16; off; off >>= 1) {
                    unsigned long long o = __shfl_xor_sync(FULLMASK, mn, off);
                    if (o < mn) mn = o;
                }
                if (v0 == mn) v0 = 0xffffffffffffffffull;
                if (v1 == mn) v1 = 0xffffffffffffffffull;
                if (lane == 0)
                    nbr[((size_t)b*4096 + q)*11 + r] = b*4096 + (int)(mn & 0xffffffffu);
            }
        } else {
            float4 Q = cand[q];
            float m2x = -2.f*Q.x, m2y = -2.f*Q.y, m2z = -2.f*Q.z;
            unsigned long long last = 0ull;
            for (int r = 0; r < 11; r++) {
                unsigned long long lm = 0xffffffffffffffffull;
                for (int m = lane; m < 4096; m += 32) {
                    float4 c = cand[m];
                    float key = fmaf(c.x, m2x, fmaf(c.y, m2y, fmaf(c.z, m2z, c.w)));
                    unsigned long long pk =
                        ((unsigned long long)orderable_f32(key) << 32) | (unsigned)m;
                    if (pk > last && pk < lm) lm = pk;
                }
                unsigned long long mn = lm;
                #pragma unroll
                for (int off = 16; off; off >>= 1) {
                    unsigned long long o = __shfl_xor_sync(FULLMASK, mn, off);
                    if (o < mn) mn = o;
                }
                last = mn;
                if (lane == 0)
                    nbr[((size_t)b*4096 + q)*11 + r] = b*4096 + (int)(mn & 0xffffffffu);
            }
        }
    }
}

// ---------------- stage-1 u/v + W2 transpose/split + stats-zero ----------------
__global__ void uv1p_kernel(const float* __restrict__ x, const float* __restrict__ W1,
                            float* __restrict__ buf1,
                            const float* __restrict__ W2, const float* __restrict__ Ws2a,
                            __nv_bfloat16* __restrict__ W2t_h, __nv_bfloat16* __restrict__ W2t_l,
                            float* __restrict__ stats)
{
    int idx = blockIdx.x*blockDim.x + threadIdx.x;
    if (idx < 3*512) stats[idx] = 0.f;
    if (idx < 384*64) {
        int n = idx/64, k = idx%64;
        float v;
        if      (n < 128) v = W2[k*128 + n];
        else if (n < 256) v = W2[(64+k)*128 + (n-128)];
        else if (n < 320) v = Ws2a[k*64 + (n-256)];
        else              v = Ws2a[(64+k)*64 + (n-320)];
        __nv_bfloat16 h, l; bsplit(v, h, l);
        W2t_h[idx] = h; W2t_l[idx] = l;
    }
    if (idx >= BNPTS*64) return;
    int n = idx >> 6, c = idx & 63;
    const float* xp = x + (size_t)n*5;
    float x0 = xp[0], x1 = xp[1], x2 = xp[2], x3 = xp[3], x4 = xp[4];
    float u = x0*W1[0*64+c] + x1*W1[1*64+c] + x2*W1[2*64+c] + x3*W1[6*64+c] + x4*W1[7*64+c];
    float v = x0*W1[3*64+c] + x1*W1[4*64+c] + x2*W1[5*64+c] + x3*W1[8*64+c] + x4*W1[9*64+c];
    buf1[n*128 + c]      = u;
    buf1[n*128 + 64 + c] = v;
}

// ---------------- prep3a: Wa1 transpose/split + pooled zero ----------------
__global__ void prep3a_kernel(const float* __restrict__ Wa1,
                              __nv_bfloat16* __restrict__ Wa1t_h,
                              __nv_bfloat16* __restrict__ Wa1t_l,
                              float* __restrict__ pooled)
{
    int j = blockIdx.x*blockDim.x + threadIdx.x;
    if (j < BB*256) pooled[j] = 0.f;
    if (j < 64*256) {
        int n = j/256, k = j%256;
        __nv_bfloat16 h, l; bsplit(Wa1[k*64 + n], h, l);
        Wa1t_h[j] = h; Wa1t_l[j] = l;
    }
}

// ---------------- prep3b: W3 transpose/split ----------------
__global__ void prep3b_kernel(const float* __restrict__ W3, const float* __restrict__ Ws3a,
                              __nv_bfloat16* __restrict__ W3t_h,
                              __nv_bfloat16* __restrict__ W3t_l)
{
    int j = blockIdx.x*blockDim.x + threadIdx.x;
    if (j < 768*128) {
        int n = j/128, k = j%128;
        float v;
        if      (n < 256) v = W3[k*256 + n];
        else if (n < 512) v = W3[(128+k)*256 + (n-256)];
        else if (n < 640) v = Ws3a[k*128 + (n-512)];
        else              v = Ws3a[(128+k)*128 + (n-640)];
        __nv_bfloat16 h, l; bsplit(v, h, l);
        W3t_h[j] = h; W3t_l[j] = l;
    }
}

// ---------------- BN statistics over edges + fused finalize (R13 version) ------
__global__ void stats_kernel(const float* __restrict__ buf, int stride, int uoff, int voff,
                             const int* __restrict__ nbr, int koff, int ppb,
                             float* __restrict__ stats, float* __restrict__ maxOut,
                             const float* __restrict__ g, const float* __restrict__ bbias,
                             float* __restrict__ scale, float* __restrict__ shift,
                             unsigned* __restrict__ ctr)
{
    const int c = threadIdx.x;
    const int C = blockDim.x;
    const int p0 = blockIdx.x * ppb;
    float sum = 0.f, ss = 0.f;
    for (int p = 0; p < ppb; p++) {
        int n = p0 + p;
        float un = buf[(size_t)n*stride + uoff + c];
        float vn = buf[(size_t)n*stride + voff + c];
        float w = vn - un;
        float mx = -3.4e38f;
        #pragma unroll
        for (int k = 0; k < KK; k++) {
            int j = nbr[n*11 + koff + k];
            float z = buf[(size_t)j*stride + uoff + c] + w;
            sum += z; ss += z*z;
            mx = fmaxf(mx, z);
        }
        if (maxOut) maxOut[(size_t)n*C + c] = mx;
    }
    atomicAdd(&stats[c], sum);
    atomicAdd(&stats[256 + c], ss);

    __threadfence();
    __shared__ unsigned done;
    if (c == 0) done = atomicAdd(ctr, 1u);
    __syncthreads();
    if (done == gridDim.x - 1) {
        float mean = stats[c] / EDGE_COUNT;
        float var  = stats[256 + c] / EDGE_COUNT - mean*mean;
        float rs = rsqrtf(var + EPS);
        float sc = g[c]*rs;
        scale[c] = sc;
        shift[c] = bbias[c] - mean*sc;
        if (c == 0) *ctr = 0;
    }
}

// ---------------- tensor GEMM: split-bf16 mma.sync, double-buffered ----------
// FUSEW: instead of storing C, compute wlog[row] = sum_c relu(C+ba1[c])*Wa2[c] + ba2
#define AROW 48   // smem row stride bytes (16 bf16 = 32B data + 16B pad)

template<int BM, int BN, int NT, bool FUSEA, bool FUSEW>
__global__ __launch_bounds__(NT) void tgemm_kernel(
    const float* __restrict__ A,
    const __nv_bfloat16* __restrict__ Bh, const __nv_bfloat16* __restrict__ Bl,
    float* __restrict__ C, int M, int N, int Kd,
    const float* __restrict__ fscale, const float* __restrict__ fshift,
    const float* __restrict__ ba1g, const float* __restrict__ Wa2g,
    const float* __restrict__ ba2g, float* __restrict__ wlogOut)
{
    constexpr int NWARP = NT/32;
    constexpr int WC = BN/32;
    constexpr int WR = BM/32;
    static_assert(WR*WC == NWARP, "warp grid mismatch");
    constexpr int ALD = (BM*16)/(4*NT);

    __shared__ __align__(16) unsigned char Ash[2][2][BM*AROW];
    __shared__ __align__(16) unsigned char Bsh[2][2][BN*AROW];
    __shared__ float wl[2][BM];

    const int tid  = threadIdx.x;
    const int warp = tid >> 5, lane = tid & 31;
    const int wr = warp / WC, wc = warp % WC;
    const int rowBase = blockIdx.x*BM, colBase = blockIdx.y*BN;

    float acc[2][4][4];
    #pragma unroll
    for (int m = 0; m < 2; m++)
        #pragma unroll
        for (int j = 0; j < 4; j++)
            #pragma unroll
            for (int r = 0; r < 4; r++) acc[m][j][r] = 0.f;

    float4 aReg[ALD];
    uint4 bRegH, bRegL;
    const bool bAct = (BN == 128) || (tid < BN*2);
    const int bn = tid >> 1, bhalf = tid & 1;

    auto LDG = [&](int k0) {
        #pragma unroll
        for (int l = 0; l < ALD; l++) {
            int i = tid + l*NT;
            int r = i >> 2, kk = (i & 3)*4;
            float4 v = *reinterpret_cast<const float4*>(
                &A[(size_t)(rowBase + r)*Kd + k0 + kk]);
            if (FUSEA) {
                float4 sc = *reinterpret_cast<const float4*>(&fscale[k0 + kk]);
                float4 sh = *reinterpret_cast<const float4*>(&fshift[k0 + kk]);
                v.x = fmaxf(fmaf(sc.x, v.x, sh.x), 0.f);
                v.y = fmaxf(fmaf(sc.y, v.y, sh.y), 0.f);
                v.z = fmaxf(fmaf(sc.z, v.z, sh.z), 0.f);
                v.w = fmaxf(fmaf(sc.w, v.w, sh.w), 0.f);
            }
            aReg[l] = v;
        }
        if (bAct) {
            size_t off = (size_t)(colBase + bn)*Kd + k0 + bhalf*8;
            bRegH = *reinterpret_cast<const uint4*>(Bh + off);
            bRegL = *reinterpret_cast<const uint4*>(Bl + off);
        }
    };
    auto STS = [&](int bf) {
        #pragma unroll
        for (int l = 0; l < ALD; l++) {
            int i = tid + l*NT;
            int r = i >> 2, kk = (i & 3)*4;
            float4 v = aReg[l];
            __nv_bfloat16 hx, lx, hy, ly, hz, lz, hw, lw;
            bsplit(v.x, hx, lx); bsplit(v.y, hy, ly);
            bsplit(v.z, hz, lz); bsplit(v.w, hw, lw);
            unsigned long long hword =
                (unsigned long long)bfpair(hx, hy)
                | ((unsigned long long)bfpair(hz, hw) << 32);
            unsigned long long lword =
                (unsigned long long)bfpair(lx, ly)
                | ((unsigned long long)bfpair(lz, lw) << 32);
            int boff = r*AROW + kk*2;
            *reinterpret_cast<unsigned long long*>(&Ash[bf][0][boff]) = hword;
            *reinterpret_cast<unsigned long long*>(&Ash[bf][1][boff]) = lword;
        }
        if (bAct) {
            int boff = bn*AROW + bhalf*16;
            *reinterpret_cast<uint4*>(&Bsh[bf][0][boff]) = bRegH;
            *reinterpret_cast<uint4*>(&Bsh[bf][1][boff]) = bRegL;
        }
    };
    auto COMPUTE = [&](int bf) {
        unsigned a[2][2][4];
        const int arow = (lane & 7) + ((lane >> 3) & 1)*8;
        const int akh  = lane >> 4;
        #pragma unroll
        for (int mi = 0; mi < 2; mi++)
            #pragma unroll
            for (int h = 0; h < 2; h++)
                ldsm4(a[mi][h][0], a[mi][h][1], a[mi][h][2], a[mi][h][3],
                      smem_u32(&Ash[bf][h][(wr*32 + mi*16 + arow)*AROW + akh*16]));
        unsigned b[2][4][2];
        const int brow = (lane & 7) + ((lane >> 4) & 1)*8;
        const int bkh  = (lane >> 3) & 1;
        #pragma unroll
        for (int bj = 0; bj < 2; bj++)
            #pragma unroll
            for (int h = 0; h < 2; h++) {
                unsigned t0, t1, t2, t3;
                ldsm4(t0, t1, t2, t3,
                      smem_u32(&Bsh[bf][h][(wc*32 + bj*16 + brow)*AROW + bkh*16]));
                b[h][bj*2+0][0] = t0; b[h][bj*2+0][1] = t1;
                b[h][bj*2+1][0] = t2; b[h][bj*2+1][1] = t3;
            }
        #pragma unroll
        for (int mi = 0; mi < 2; mi++)
            #pragma unroll
            for (int j = 0; j < 4; j++) {
                mma_bf16(acc[mi][j], a[mi][0], b[0][j]);
                mma_bf16(acc[mi][j], a[mi][0], b[1][j]);
                mma_bf16(acc[mi][j], a[mi][1], b[0][j]);
            }
    };

    const int nch = Kd / 16;
    LDG(0);
    STS(0);
    __syncthreads();
    for (int c = 0; c < nch; c++) {
        int cur = c & 1;
        if (c + 1 < nch) LDG((c + 1)*16);
        COMPUTE(cur);
        if (c + 1 < nch) STS(cur ^ 1);
        __syncthreads();
    }

    if (FUSEW) {
        // wlog epilogue: per-row sum of relu(acc + ba1[col]) * Wa2[col]
        float part[2][2];
        part[0][0] = part[0][1] = part[1][0] = part[1][1] = 0.f;
        #pragma unroll
        for (int j = 0; j < 4; j++) {
            int c0 = wc*32 + j*8 + (lane & 3)*2;
            float b0 = ba1g[c0], b1 = ba1g[c0+1];
            float w0 = Wa2g[c0], w1 = Wa2g[c0+1];
            #pragma unroll
            for (int mi = 0; mi < 2; mi++) {
                part[mi][0] += fmaxf(acc[mi][j][0] + b0, 0.f)*w0
                             + fmaxf(acc[mi][j][1] + b1, 0.f)*w1;
                part[mi][1] += fmaxf(acc[mi][j][2] + b0, 0.f)*w0
                             + fmaxf(acc[mi][j][3] + b1, 0.f)*w1;
            }
        }
        #pragma unroll
        for (int mi = 0; mi < 2; mi++)
            #pragma unroll
            for (int h = 0; h < 2; h++) {
                part[mi][h] += __shfl_xor_sync(FULLMASK, part[mi][h], 1);
                part[mi][h] += __shfl_xor_sync(FULLMASK, part[mi][h], 2);
            }
        if ((lane & 3) == 0) {
            #pragma unroll
            for (int mi = 0; mi < 2; mi++)
                #pragma unroll
                for (int h = 0; h < 2; h++)
                    wl[wc][wr*32 + mi*16 + (lane >> 2) + h*8] = part[mi][h];
        }
        __syncthreads();
        if (tid < BM)
            wlogOut[rowBase + tid] = wl[0][tid] + wl[1][tid] + ba2g[0];
    } else {
        #pragma unroll
        for (int mi = 0; mi < 2; mi++)
            #pragma unroll
            for (int j = 0; j < 4; j++) {
                int row0 = rowBase + wr*32 + mi*16 + (lane >> 2);
                int col  = colBase + wc*32 + j*8 + (lane & 3)*2;
                float2 p0; p0.x = acc[mi][j][0]; p0.y = acc[mi][j][1];
                float2 p1; p1.x = acc[mi][j][2]; p1.y = acc[mi][j][3];
                *reinterpret_cast<float2*>(&C[(size_t)row0*N + col]) = p0;
                *reinterpret_cast<float2*>(&C[(size_t)(row0 + 8)*N + col]) = p1;
            }
    }
}

// ---------------- soft-edge aggregation (parallel softmax) ----------------
template<int C, int CA>
__global__ void softedge_kernel(const float* __restrict__ buf, const int* __restrict__ nbr,
                                const float* __restrict__ scale, const float* __restrict__ shift,
                                const float* __restrict__ ab,
                                const float* __restrict__ Wb, const float* __restrict__ bb,
                                float* __restrict__ fout)
{
    constexpr int STRIDE = 2*C + 2*CA;
    constexpr int AOFF = 2*C;
    const int n = blockIdx.x;
    const int t = threadIdx.x;

    __shared__ int   js[KK];
    __shared__ float wps[KK][C/32];
    __shared__ float alpha[KK];

    if (t < KK) js[t] = nbr[n*11 + 1 + t];
    __syncthreads();

    float base_a = 0.f;
    if (t < CA) {
        float usn = buf[(size_t)n*STRIDE + AOFF + t];
        base_a = buf[(size_t)n*STRIDE + AOFF + CA + t] - usn + ab[t];
    }
    #pragma unroll
    for (int k = 0; k < KK; k++) {
        float v = 0.f;
        if (t < CA) {
            float h = buf[(size_t)js[k]*STRIDE + AOFF + t] + base_a;
            h = fmaxf(h, 0.f);
            v = h * Wb[t];
        }
        #pragma unroll
        for (int off = 16; off; off >>= 1) v += __shfl_down_sync(FULLMASK, v, off);
        if ((t & 31) == 0) wps[k][t >> 5] = v;
    }
    __syncthreads();
    if (t < KK) {
        float s = 0.f;
        #pragma unroll
        for (int w = 0; w < C/32; w++) s += wps[t][w];
        alpha[t] = (s + bb[0]) / TAU;
    }
    __syncthreads();
    if (t < 32) {
        float v = (t < KK) ? alpha[t] : -3.4e38f;
        float mx = v;
        #pragma unroll
        for (int off = 16; off; off >>= 1)
            mx = fmaxf(mx, __shfl_xor_sync(FULLMASK, mx, off));
        float e = (t < KK) ? expf(v - mx) : 0.f;
        float s = e;
        #pragma unroll
        for (int off = 16; off; off >>= 1) s += __shfl_xor_sync(FULLMASK, s, off);
        if (t < KK) alpha[t] = e / s;
    }
    __syncthreads();

    float un = buf[(size_t)n*STRIDE + t];
    float w  = buf[(size_t)n*STRIDE + C + t] - un;
    float sc = scale[t], sh = shift[t];
    float acc = 0.f;
    #pragma unroll
    for (int k = 0; k < KK; k++) {
        float z = buf[(size_t)js[k]*STRIDE + t] + w;
        acc += alpha[k] * fmaxf(sc*z + sh, 0.f);
    }
    fout[(size_t)n*C + t] = acc;
}

// ---------------- final attention pooling ----------------
__global__ void batred_kernel(const float* __restrict__ wlog, float* __restrict__ bmax,
                              float* __restrict__ bsum)
{
    int b = blockIdx.x, t = threadIdx.x;
    __shared__ float red[256];
    float mx = -3.4e38f;
    for (int n = t; n < NN; n += 256) mx = fmaxf(mx, wlog[b*NN + n]);
    red[t] = mx; __syncthreads();
    for (int s = 128; s; s >>= 1) { if (t < s) red[t] = fmaxf(red[t], red[t+s]); __syncthreads(); }
    float M = red[0]; __syncthreads();
    float s = 0.f;
    for (int n = t; n < NN; n += 256) s += expf(wlog[b*NN + n] - M);
    red[t] = s; __syncthreads();
    for (int st = 128; st; st >>= 1) { if (t < st) red[t] += red[t+st]; __syncthreads(); }
    if (t == 0) { bmax[b] = M; bsum[b] = red[0]; }
}

__global__ void pool_kernel(const float* __restrict__ f3, const float* __restrict__ wlog,
                            const float* __restrict__ bmax, const float* __restrict__ bsum,
                            float* __restrict__ pooled)
{
    int b = blockIdx.y, t = threadIdx.x;
    int n0 = blockIdx.x * 256;
    __shared__ float ew[256];
    ew[t] = expf(wlog[b*NN + n0 + t] - bmax[b]) / bsum[b];
    __syncthreads();
    float acc = 0.f;
    for (int i = 0; i < 256; i++)
        acc += ew[i] * f3[((size_t)b*NN + n0 + i)*256 + t];
    atomicAdd(&pooled[b*256 + t], acc);
}

__global__ void final_kernel(const float* __restrict__ pooled, const float* __restrict__ Wfc,
                             const float* __restrict__ bfc, float* __restrict__ out)
{
    int b = blockIdx.x, t = threadIdx.x;
    __shared__ float p[256];
    p[t] = pooled[b*256 + t];
    __syncthreads();
    float acc = bfc[t];
    for (int i = 0; i < 256; i++) acc = fmaf(p[i], Wfc[i*256 + t], acc);
    out[b*256 + t] = fmaxf(acc, 0.f);
}

// ---------------- host launcher ----------------
static void* sym_addr_helper(const void* symbol)
{
    void* p = nullptr;
    cudaGetSymbolAddress(&p, symbol);
    return p;
}

extern "C" void kernel_launch(void* const* d_in, const int* in_sizes, int n_in,
                              void* d_out, int out_size)
{
    const float* x    = (const float*)d_in[0];
    const float* W1   = (const float*)d_in[1];
    const float* g1   = (const float*)d_in[2];
    const float* b1   = (const float*)d_in[3];
    const float* W2   = (const float*)d_in[4];
    const float* g2   = (const float*)d_in[5];
    const float* b2   = (const float*)d_in[6];
    const float* Ws2a = (const float*)d_in[7];
    const float* bs2a = (const float*)d_in[8];
    const float* Ws2b = (const float*)d_in[9];
    const float* bs2b = (const float*)d_in[10];
    const float* W3   = (const float*)d_in[11];
    const float* g3   = (const float*)d_in[12];
    const float* b3   = (const float*)d_in[13];
    const float* Ws3a = (const float*)d_in[14];
    const float* bs3a = (const float*)d_in[15];
    const float* Ws3b = (const float*)d_in[16];
    const float* bs3b = (const float*)d_in[17];
    const float* Wa1  = (const float*)d_in[18];
    const float* ba1  = (const float*)d_in[19];
    const float* Wa2  = (const float*)d_in[20];
    const float* ba2  = (const float*)d_in[21];
    const float* Wfc  = (const float*)d_in[22];
    const float* bfc  = (const float*)d_in[23];
    float* out = (float*)d_out;
    (void)in_sizes; (void)n_in; (void)out_size;

    int*      nbr    = (int*)     sym_addr_helper(d_nbr);
    float*    buf1   = (float*)   sym_addr_helper(d_buf1);
    float*    m1     = (float*)   sym_addr_helper(d_m1);
    float*    buf2   = (float*)   sym_addr_helper(d_buf2);
    float*    f2     = (float*)   sym_addr_helper(d_f2);
    float*    buf3   = (float*)   sym_addr_helper(d_buf3);
    float*    f3     = (float*)   sym_addr_helper(d_f3);
    __nv_bfloat16* W2t_h  = (__nv_bfloat16*)sym_addr_helper(d_W2t_h);
    __nv_bfloat16* W2t_l  = (__nv_bfloat16*)sym_addr_helper(d_W2t_l);
    __nv_bfloat16* W3t_h  = (__nv_bfloat16*)sym_addr_helper(d_W3t_h);
    __nv_bfloat16* W3t_l  = (__nv_bfloat16*)sym_addr_helper(d_W3t_l);
    __nv_bfloat16* Wa1t_h = (__nv_bfloat16*)sym_addr_helper(d_Wa1t_h);
    __nv_bfloat16* Wa1t_l = (__nv_bfloat16*)sym_addr_helper(d_Wa1t_l);
    float*    stats  = (float*)   sym_addr_helper(d_stats);
    float*    scale  = (float*)   sym_addr_helper(d_scale);
    float*    shift  = (float*)   sym_addr_helper(d_shift);
    unsigned* ctr    = (unsigned*)sym_addr_helper(d_ctr);
    float*    wlog   = (float*)   sym_addr_helper(d_wlog);
    float*    bmax   = (float*)   sym_addr_helper(d_bmax);
    float*    bsum   = (float*)   sym_addr_helper(d_bsum);
    float*    pooled = (float*)   sym_addr_helper(d_pooled);

    cudaFuncSetAttribute(knn_kernel, cudaFuncAttributeMaxDynamicSharedMemorySize, KNN_SMEM);

    // launch order: uv1p(1), prep3a(2), prep3b(3), knn(4) <- ncu capture slot
    uv1p_kernel<<<BNPTS*64/256, 256>>>(x, W1, buf1, W2, Ws2a, W2t_h, W2t_l, stats);
    prep3a_kernel<<<(64*256 + 255)/256, 256>>>(Wa1, Wa1t_h, Wa1t_l, pooled);
    prep3b_kernel<<<(768*128 + 255)/256, 256>>>(W3, Ws3a, W3t_h, W3t_l);
    knn_kernel<<<dim3(4096/(KNN_WARPS*KNN_QB), BB), KNN_WARPS*32, KNN_SMEM>>>(x, nbr);

    // stage 1 (finalize fused into stats; f1 fused into gemm2's A-load)
    stats_kernel<<<BNPTS/16, 64>>>(buf1, 128, 0, 64, nbr, 0, 16, stats, m1,
                                   g1, b1, scale, shift, ctr);

    // stage 2 (tensor GEMM)
    tgemm_kernel<64,128,256,true,false><<<dim3(BNPTS/64, 3), 256>>>(
        m1, W2t_h, W2t_l, buf2, BNPTS, 384, 64, scale, shift,
        nullptr, nullptr, nullptr, nullptr);
    stats_kernel<<<BNPTS/16, 128>>>(buf2, 384, 0, 128, nbr, 1, 16, stats + 512, nullptr,
                                    g2, b2, scale + 256, shift + 256, ctr + 1);
    softedge_kernel<128,64><<<BNPTS, 128>>>(buf2, nbr, scale + 256, shift + 256, bs2a, Ws2b, bs2b, f2);

    // stage 3 (tensor GEMM)
    tgemm_kernel<64,128,256,false,false><<<dim3(BNPTS/64, 6), 256>>>(
        f2, W3t_h, W3t_l, buf3, BNPTS, 768, 128, nullptr, nullptr,
        nullptr, nullptr, nullptr, nullptr);
    stats_kernel<<<BNPTS/8, 256>>>(buf3, 768, 0, 256, nbr, 1, 8, stats + 1024, nullptr,
                                   g3, b3, scale + 512, shift + 512, ctr + 2);
    softedge_kernel<256,128><<<BNPTS, 256>>>(buf3, nbr, scale + 512, shift + 512, bs3a, Ws3b, bs3b, f3);

    // attention pooling + head: hall GEMM with fused wlog epilogue
    tgemm_kernel<128,64,256,false,true><<<dim3(BNPTS/128, 1), 256>>>(
        f3, Wa1t_h, Wa1t_l, nullptr, BNPTS, 64, 256, nullptr, nullptr,
        ba1, Wa2, ba2, wlog);
    batred_kernel<<<BB, 256>>>(wlog, bmax, bsum);
    pool_kernel<<<dim3(NN/256, BB), 256>>>(f3, wlog, bmax, bsum, pooled);
    final_kernel<<<BB, 256>>>(pooled, Wfc, bfc, out);
}